// round 11
// baseline (speedup 1.0000x reference)
#include <cuda_runtime.h>
#include <cstdint>

// ---------------- problem constants ----------------
#define E_MAX 100000
#define T_MAX 200000
#define H 128
#define NR 16
#define NSR 112
#define NB 8

// ---------------- scratch ----------------
__device__ float g_h   [(size_t)E_MAX * H];
__device__ float g_xkj [(size_t)E_MAX * H];
__device__ float g_wt  [(size_t)9 * H * H];      // 9 transposed+rounded weights [n][k]
__device__ float g_bw  [(size_t)H * NB * H];     // tf32-rounded bil_W copy

// ---------------- helpers ----------------
__device__ __forceinline__ float tf32r(float x) {
    float y; asm("cvt.rna.tf32.f32 %0, %1;" : "=f"(y) : "f"(x)); return y;
}
__device__ __forceinline__ uint32_t cvu(float x) { return __float_as_uint(tf32r(x)); }
__device__ __forceinline__ float silu_f(float v) {
    return v * (1.0f / (1.0f + __expf(-v)));
}
__device__ __forceinline__ void mma_tf32(float* c, const uint32_t* a, const uint32_t* b) {
    asm volatile(
        "mma.sync.aligned.m16n8k8.row.col.f32.tf32.tf32.f32 "
        "{%0,%1,%2,%3}, {%4,%5,%6,%7}, {%8,%9}, {%0,%1,%2,%3};"
        : "+f"(c[0]), "+f"(c[1]), "+f"(c[2]), "+f"(c[3])
        : "r"(a[0]), "r"(a[1]), "r"(a[2]), "r"(a[3]), "r"(b[0]), "r"(b[1]));
}

#define BP 132      // tile pitch (floats), 132 % 32 == 4 -> conflict-free frags
#define TILE_B (128 * BP * 4)   // 67584 bytes

// ---------------- shared GEMM building blocks (512 thr, warps 4m x 4n) ----------
__device__ __forceinline__ void acc_zero(float acc[2][4][4]) {
#pragma unroll
    for (int i = 0; i < 2; i++)
#pragma unroll
        for (int j = 0; j < 4; j++)
#pragma unroll
            for (int e = 0; e < 4; e++) acc[i][j][e] = 0.f;
}

// acc += At(pre-rounded) @ Bs(pre-rounded [n][k])^T  — pure LDS+MMA inner loop
__device__ __forceinline__ void mma_128(const float* __restrict__ At,
                                        const float* __restrict__ Bs,
                                        float acc[2][4][4],
                                        int r0, int ncol, int g, int t4)
{
#pragma unroll
    for (int ks = 0; ks < 16; ks++) {
        const int k0 = ks * 8;
        uint32_t a[2][4], bb[4][2];
        a[0][0] = __float_as_uint(At[(r0)      * BP + k0 + t4]);
        a[0][1] = __float_as_uint(At[(r0 + 8)  * BP + k0 + t4]);
        a[0][2] = __float_as_uint(At[(r0)      * BP + k0 + t4 + 4]);
        a[0][3] = __float_as_uint(At[(r0 + 8)  * BP + k0 + t4 + 4]);
        a[1][0] = __float_as_uint(At[(r0 + 16) * BP + k0 + t4]);
        a[1][1] = __float_as_uint(At[(r0 + 24) * BP + k0 + t4]);
        a[1][2] = __float_as_uint(At[(r0 + 16) * BP + k0 + t4 + 4]);
        a[1][3] = __float_as_uint(At[(r0 + 24) * BP + k0 + t4 + 4]);
#pragma unroll
        for (int j = 0; j < 4; j++) {
            int c0 = ncol + j * 8 + g;
            bb[j][0] = __float_as_uint(Bs[c0 * BP + k0 + t4]);
            bb[j][1] = __float_as_uint(Bs[c0 * BP + k0 + t4 + 4]);
        }
#pragma unroll
        for (int i = 0; i < 2; i++)
#pragma unroll
            for (int j = 0; j < 4; j++)
                mma_tf32(acc[i][j], a[i], bb[j]);
    }
}

__device__ __forceinline__ void stage_w(float* Bs, const float* __restrict__ W, int tid) {
#pragma unroll
    for (int i = 0; i < 8; i++) {
        int idx = i * 512 + tid;
        int r = idx >> 5, c4 = idx & 31;
        *(float4*)&Bs[r * BP + c4 * 4] = *(const float4*)&W[(size_t)r * H + c4 * 4];
    }
}
// stage + tf32-round
__device__ __forceinline__ void stage_tile_r(float* Tt, const float* __restrict__ A,
                                             int rowBase, int M, int tid) {
#pragma unroll
    for (int i = 0; i < 8; i++) {
        int idx = i * 512 + tid;
        int r = idx >> 5, c4 = idx & 31;
        int grow = rowBase + r;
        float4 v = (grow < M) ? *(const float4*)&A[(size_t)grow * H + c4 * 4]
                              : make_float4(0.f, 0.f, 0.f, 0.f);
        v.x = tf32r(v.x); v.y = tf32r(v.y); v.z = tf32r(v.z); v.w = tf32r(v.w);
        *(float4*)&Tt[r * BP + c4 * 4] = v;
    }
}
// tile <- round(silu(acc + bias))
__device__ __forceinline__ void epi_to_tile(float* Tt, const float acc[2][4][4],
                                            const float* biasS,
                                            int mrow, int ncol, int g, int t4)
{
#pragma unroll
    for (int i = 0; i < 2; i++)
#pragma unroll
        for (int half = 0; half < 2; half++) {
            int row = mrow + i * 16 + half * 8 + g;
#pragma unroll
            for (int j = 0; j < 4; j++) {
                int col = ncol + j * 8 + t4 * 2;
                float v0 = tf32r(silu_f(acc[i][j][half * 2 + 0] + biasS[col]));
                float v1 = tf32r(silu_f(acc[i][j][half * 2 + 1] + biasS[col + 1]));
                *(float2*)&Tt[row * BP + col] = make_float2(v0, v1);
            }
        }
}

// ================= fused x_ji / x_kj / rbf_h kernel ==============================
#define FJ_T0   0
#define FJ_BS   TILE_B
#define FJ_RB   (2 * TILE_B)
#define FJ_BIAS (3 * TILE_B)
#define FJ_SMEM (FJ_BIAS + 1024)
#define RP 20

__global__ void __launch_bounds__(512, 1)
fused_jikj(const float* __restrict__ x, const float* __restrict__ rbf,
           const float* __restrict__ rbfW,
           const float* __restrict__ kjWt, const float* __restrict__ kjb,
           const float* __restrict__ jiWt, const float* __restrict__ jib,
           float* __restrict__ xkj_out, float* __restrict__ h_out, int M)
{
    extern __shared__ char smem[];
    float* T0 = (float*)(smem + FJ_T0);
    float* Bs = (float*)(smem + FJ_BS);
    float* RB = (float*)(smem + FJ_RB);
    float* bKj = (float*)(smem + FJ_BIAS);
    float* bJi = (float*)(smem + FJ_BIAS + 512);
    float* rtile = Bs;                  // [128][RP] (temp, before kj weight staged)
    float* rw    = Bs + 128 * RP;       // [128][RP]
    const int tid = threadIdx.x;
    const int wid = tid >> 5, lane = tid & 31;
    const int g = lane >> 2, t4 = lane & 3;
    const int rowBase = blockIdx.x * 128;
    const int mrow = (wid & 3) * 32;
    const int ncol = (wid >> 2) * 32;
    const int r0 = mrow + g;

    stage_tile_r(T0, x, rowBase, M, tid);
    // rbf A tile [128][16] (pitch RP), pre-rounded
    {
        int r = tid >> 2, c4 = tid & 3;
        int grow = rowBase + r;
        float4 v = (grow < M) ? *(const float4*)&rbf[(size_t)grow * NR + c4 * 4]
                              : make_float4(0.f, 0.f, 0.f, 0.f);
        v.x = tf32r(v.x); v.y = tf32r(v.y); v.z = tf32r(v.z); v.w = tf32r(v.w);
        *(float4*)&rtile[r * RP + c4 * 4] = v;
    }
    // rbf_W^T pre-rounded: rw[n*RP + k] = rbfW[k*128 + n]
    {
        int n = tid >> 2, k0 = (tid & 3) * 4;
#pragma unroll
        for (int e = 0; e < 4; e++)
            rw[n * RP + k0 + e] = tf32r(rbfW[(size_t)(k0 + e) * H + n]);
    }
    if (tid < 32)       *(float4*)&bKj[tid * 4] = *(const float4*)&kjb[tid * 4];
    else if (tid < 64)  *(float4*)&bJi[(tid - 32) * 4] = *(const float4*)&jib[(tid - 32) * 4];
    __syncthreads();

    // rbf_h tile = rbf @ rbf_W   (K=16, 2 ks steps)
    float acc[2][4][4];
    acc_zero(acc);
#pragma unroll
    for (int ks = 0; ks < 2; ks++) {
        const int k0 = ks * 8;
        uint32_t a[2][4], bb[4][2];
        a[0][0] = __float_as_uint(rtile[(r0)      * RP + k0 + t4]);
        a[0][1] = __float_as_uint(rtile[(r0 + 8)  * RP + k0 + t4]);
        a[0][2] = __float_as_uint(rtile[(r0)      * RP + k0 + t4 + 4]);
        a[0][3] = __float_as_uint(rtile[(r0 + 8)  * RP + k0 + t4 + 4]);
        a[1][0] = __float_as_uint(rtile[(r0 + 16) * RP + k0 + t4]);
        a[1][1] = __float_as_uint(rtile[(r0 + 24) * RP + k0 + t4]);
        a[1][2] = __float_as_uint(rtile[(r0 + 16) * RP + k0 + t4 + 4]);
        a[1][3] = __float_as_uint(rtile[(r0 + 24) * RP + k0 + t4 + 4]);
#pragma unroll
        for (int j = 0; j < 4; j++) {
            int c0 = ncol + j * 8 + g;
            bb[j][0] = __float_as_uint(rw[c0 * RP + k0 + t4]);
            bb[j][1] = __float_as_uint(rw[c0 * RP + k0 + t4 + 4]);
        }
#pragma unroll
        for (int i = 0; i < 2; i++)
#pragma unroll
            for (int j = 0; j < 4; j++)
                mma_tf32(acc[i][j], a[i], bb[j]);
    }
    __syncthreads();   // done reading rtile/rw (Bs region)

    // write rbf_h to RB tile (full fp32, epilogue multiplier); stage kj weight
#pragma unroll
    for (int i = 0; i < 2; i++)
#pragma unroll
        for (int half = 0; half < 2; half++) {
            int row = mrow + i * 16 + half * 8 + g;
#pragma unroll
            for (int j = 0; j < 4; j++) {
                int col = ncol + j * 8 + t4 * 2;
                *(float2*)&RB[row * BP + col] =
                    make_float2(acc[i][j][half * 2], acc[i][j][half * 2 + 1]);
            }
        }
    stage_w(Bs, kjWt, tid);
    __syncthreads();

    // x_kj = silu(silu(x@kjW+b)) * rbf_h
    acc_zero(acc);
    mma_128(T0, Bs, acc, r0, ncol, g, t4);
#pragma unroll
    for (int i = 0; i < 2; i++)
#pragma unroll
        for (int half = 0; half < 2; half++) {
            int row = mrow + i * 16 + half * 8 + g;
            int grow = rowBase + row;
            if (grow >= M) continue;
#pragma unroll
            for (int j = 0; j < 4; j++) {
                int col = ncol + j * 8 + t4 * 2;
                float v0 = silu_f(silu_f(acc[i][j][half * 2 + 0] + bKj[col]));
                float v1 = silu_f(silu_f(acc[i][j][half * 2 + 1] + bKj[col + 1]));
                float2 m = *(float2*)&RB[row * BP + col];
                *(float2*)&xkj_out[(size_t)grow * H + col] = make_float2(v0 * m.x, v1 * m.y);
            }
        }
    __syncthreads();
    stage_w(Bs, jiWt, tid);
    __syncthreads();

    // x_ji = silu(silu(x@jiW+b))
    acc_zero(acc);
    mma_128(T0, Bs, acc, r0, ncol, g, t4);
#pragma unroll
    for (int i = 0; i < 2; i++)
#pragma unroll
        for (int half = 0; half < 2; half++) {
            int row = mrow + i * 16 + half * 8 + g;
            int grow = rowBase + row;
            if (grow >= M) continue;
#pragma unroll
            for (int j = 0; j < 4; j++) {
                int col = ncol + j * 8 + t4 * 2;
                float v0 = silu_f(silu_f(acc[i][j][half * 2 + 0] + bJi[col]));
                float v1 = silu_f(silu_f(acc[i][j][half * 2 + 1] + bJi[col + 1]));
                *(float2*)&h_out[(size_t)grow * H + col] = make_float2(v0, v1);
            }
        }
}

// ================= fused pre-chain: 3 GEMMs ======================================
#define FP_T0   0
#define FP_T1   TILE_B
#define FP_BS   (2 * TILE_B)
#define FP_BIAS (3 * TILE_B)
#define FP_SMEM (FP_BIAS + 2048)

__global__ void __launch_bounds__(512, 1)
fused_pre(const float* __restrict__ h, const float* __restrict__ x,
          const float* __restrict__ W1t, const float* __restrict__ b1,
          const float* __restrict__ W2t, const float* __restrict__ b2,
          const float* __restrict__ W3t, const float* __restrict__ b3,
          float* __restrict__ outg, int M)
{
    extern __shared__ char smem[];
    float* T0 = (float*)(smem + FP_T0);
    float* T1 = (float*)(smem + FP_T1);
    float* Bs = (float*)(smem + FP_BS);
    float* bS1 = (float*)(smem + FP_BIAS);
    float* bS2 = bS1 + 128;
    float* bS3 = bS2 + 128;
    const int tid = threadIdx.x;
    const int wid = tid >> 5, lane = tid & 31;
    const int g = lane >> 2, t4 = lane & 3;
    const int rowBase = blockIdx.x * 128;
    const int mrow = (wid & 3) * 32;
    const int ncol = (wid >> 2) * 32;
    const int r0 = mrow + g;

    stage_tile_r(T0, h, rowBase, M, tid);
    if (tid < 32)       *(float4*)&bS1[tid * 4] = *(const float4*)&b1[tid * 4];
    else if (tid < 64)  *(float4*)&bS2[(tid - 32) * 4] = *(const float4*)&b2[(tid - 32) * 4];
    else if (tid < 96)  *(float4*)&bS3[(tid - 64) * 4] = *(const float4*)&b3[(tid - 64) * 4];
    stage_w(Bs, W1t, tid);
    __syncthreads();

    float acc[2][4][4];
    acc_zero(acc);
    mma_128(T0, Bs, acc, r0, ncol, g, t4);
    __syncthreads();
    epi_to_tile(T1, acc, bS1, mrow, ncol, g, t4);        // u (rounded)
    stage_w(Bs, W2t, tid);
    __syncthreads();

    acc_zero(acc);
    mma_128(T1, Bs, acc, r0, ncol, g, t4);
    __syncthreads();
    // v = h + silu(u@W2+b2)  -> T1 (rounded; h from rounded T0)
#pragma unroll
    for (int i = 0; i < 2; i++)
#pragma unroll
        for (int half = 0; half < 2; half++) {
            int row = mrow + i * 16 + half * 8 + g;
#pragma unroll
            for (int j = 0; j < 4; j++) {
                int col = ncol + j * 8 + t4 * 2;
                float2 res = *(float2*)&T0[row * BP + col];
                float v0 = tf32r(res.x + silu_f(acc[i][j][half * 2 + 0] + bS2[col]));
                float v1 = tf32r(res.y + silu_f(acc[i][j][half * 2 + 1] + bS2[col + 1]));
                *(float2*)&T1[row * BP + col] = make_float2(v0, v1);
            }
        }
    stage_w(Bs, W3t, tid);
    __syncthreads();

    acc_zero(acc);
    mma_128(T1, Bs, acc, r0, ncol, g, t4);
    // out0 = silu(v@W3+b3) + x   (x fp32 from global)
#pragma unroll
    for (int i = 0; i < 2; i++)
#pragma unroll
        for (int half = 0; half < 2; half++) {
            int row = mrow + i * 16 + half * 8 + g;
            int grow = rowBase + row;
            if (grow >= M) continue;
#pragma unroll
            for (int j = 0; j < 4; j++) {
                int col = ncol + j * 8 + t4 * 2;
                float2 xr = *(const float2*)&x[(size_t)grow * H + col];
                float v0 = silu_f(acc[i][j][half * 2 + 0] + bS3[col]) + xr.x;
                float v1 = silu_f(acc[i][j][half * 2 + 1] + bS3[col + 1]) + xr.y;
                *(float2*)&outg[(size_t)grow * H + col] = make_float2(v0, v1);
            }
        }
}

// ================= fused post-chain: 4 GEMMs =====================================
__global__ void __launch_bounds__(512, 1)
fused_post(const float* __restrict__ h,
           const float* __restrict__ W1t, const float* __restrict__ b1,
           const float* __restrict__ W2t, const float* __restrict__ b2,
           const float* __restrict__ W3t, const float* __restrict__ b3,
           const float* __restrict__ W4t, const float* __restrict__ b4,
           float* __restrict__ outg, int M)
{
    extern __shared__ char smem[];
    float* T0 = (float*)(smem + FP_T0);
    float* T1 = (float*)(smem + FP_T1);
    float* Bs = (float*)(smem + FP_BS);
    float* bS1 = (float*)(smem + FP_BIAS);
    float* bS2 = bS1 + 128;
    float* bS3 = bS2 + 128;
    float* bS4 = bS3 + 128;
    const int tid = threadIdx.x;
    const int wid = tid >> 5, lane = tid & 31;
    const int g = lane >> 2, t4 = lane & 3;
    const int rowBase = blockIdx.x * 128;
    const int mrow = (wid & 3) * 32;
    const int ncol = (wid >> 2) * 32;
    const int r0 = mrow + g;

    stage_tile_r(T0, h, rowBase, M, tid);
    if (tid < 32)       *(float4*)&bS1[tid * 4] = *(const float4*)&b1[tid * 4];
    else if (tid < 64)  *(float4*)&bS2[(tid - 32) * 4] = *(const float4*)&b2[(tid - 32) * 4];
    else if (tid < 96)  *(float4*)&bS3[(tid - 64) * 4] = *(const float4*)&b3[(tid - 64) * 4];
    else if (tid < 128) *(float4*)&bS4[(tid - 96) * 4] = *(const float4*)&b4[(tid - 96) * 4];
    stage_w(Bs, W1t, tid);
    __syncthreads();

    float acc[2][4][4];
    acc_zero(acc);
    mma_128(T0, Bs, acc, r0, ncol, g, t4);
    __syncthreads();
    epi_to_tile(T1, acc, bS1, mrow, ncol, g, t4);        // u2
    stage_w(Bs, W2t, tid);
    __syncthreads();

    acc_zero(acc);
    mma_128(T1, Bs, acc, r0, ncol, g, t4);
    __syncthreads();
    // out1 = out0 + silu(u2@W2+b2)  -> overwrite T0 (rounded)
#pragma unroll
    for (int i = 0; i < 2; i++)
#pragma unroll
        for (int half = 0; half < 2; half++) {
            int row = mrow + i * 16 + half * 8 + g;
#pragma unroll
            for (int j = 0; j < 4; j++) {
                int col = ncol + j * 8 + t4 * 2;
                float2 res = *(float2*)&T0[row * BP + col];
                float v0 = tf32r(res.x + silu_f(acc[i][j][half * 2 + 0] + bS2[col]));
                float v1 = tf32r(res.y + silu_f(acc[i][j][half * 2 + 1] + bS2[col + 1]));
                *(float2*)&T0[row * BP + col] = make_float2(v0, v1);
            }
        }
    stage_w(Bs, W3t, tid);
    __syncthreads();

    acc_zero(acc);
    mma_128(T0, Bs, acc, r0, ncol, g, t4);
    __syncthreads();
    epi_to_tile(T1, acc, bS3, mrow, ncol, g, t4);        // u3
    stage_w(Bs, W4t, tid);
    __syncthreads();

    acc_zero(acc);
    mma_128(T1, Bs, acc, r0, ncol, g, t4);
    // out = out1 + silu(u3@W4+b4)
#pragma unroll
    for (int i = 0; i < 2; i++)
#pragma unroll
        for (int half = 0; half < 2; half++) {
            int row = mrow + i * 16 + half * 8 + g;
            int grow = rowBase + row;
            if (grow >= M) continue;
#pragma unroll
            for (int j = 0; j < 4; j++) {
                int col = ncol + j * 8 + t4 * 2;
                float2 res = *(float2*)&T0[row * BP + col];
                float v0 = res.x + silu_f(acc[i][j][half * 2 + 0] + bS4[col]);
                float v1 = res.y + silu_f(acc[i][j][half * 2 + 1] + bS4[col + 1]);
                *(float2*)&outg[(size_t)grow * H + col] = make_float2(v0, v1);
            }
        }
}

// ================= fused triplet: B from L2 via __ldg, barrier-free mainloop =====
// 64 triplets x 128 cols, 256 threads, 8 warps (2m x 4n), warp tile 32x32.
// SMEM holds only gathered raw rows (+ prologue buffers) — no B buffer.
#define TLJ   0                        // ji   [64] int
#define TLK   256                      // ekj  [64] int
#define TLS   512                      // sbf_s [64][8]     2 KB
#define TLW   2560                     // ws_s  [112][8]    3.5 KB
#define TLRAW 6144                     // raw  [64][BP]     33792 B (stile aliases this)
#define TL_SMEM (TLRAW + 64 * BP * 4)  // 39936 B
#define SP 113                         // sbf staging pitch: 112 cols + 1 pad

__global__ void __launch_bounds__(256, 2)
triplet_fused(const float* __restrict__ xkj,
              const float* __restrict__ sbf, const float* __restrict__ sbfW,
              const int* __restrict__ kj, const int* __restrict__ ji,
              const float* __restrict__ bw, float* __restrict__ hout, int T)
{
    extern __shared__ char smem[];
    int* ji_s = (int*)(smem + TLJ);
    int* ek_s = (int*)(smem + TLK);
    float* sbf_s = (float*)(smem + TLS);
    float* ws_s = (float*)(smem + TLW);
    float* raw = (float*)(smem + TLRAW);
    float* stile = raw;                 // [64][SP] sbf staging, 28.9KB <= raw region
    const int tid = threadIdx.x;
    const int wid = tid >> 5, lane = tid & 31;
    const int g = lane >> 2, t4 = lane & 3;
    const int tBase = blockIdx.x * 64;
    const int mrow = (wid & 1) * 32;
    const int ncol = (wid >> 1) * 32;
    const int r0 = mrow + g;

    if (tid < 64) {
        int t = tBase + tid;
        ji_s[tid] = (t < T) ? ji[t] : 0;
        ek_s[tid] = (t < T) ? kj[t] : 0;
    }
    // stage sbf_W [112][8]  (224 float4)
    if (tid < 224) *(float4*)&ws_s[tid * 4] = *(const float4*)&sbfW[tid * 4];
    // stage sbf tile [64][112] (pitch SP=113): 64*28 = 1792 float4
#pragma unroll
    for (int i = 0; i < 7; i++) {
        int idx = i * 256 + tid;
        int r = idx / 28, c = idx % 28;
        int t = tBase + r;
        float4 v = (t < T) ? *(const float4*)&sbf[(size_t)t * NSR + c * 4]
                           : make_float4(0.f, 0.f, 0.f, 0.f);
        stile[r * SP + c * 4 + 0] = v.x;
        stile[r * SP + c * 4 + 1] = v.y;
        stile[r * SP + c * 4 + 2] = v.z;
        stile[r * SP + c * 4 + 3] = v.w;
    }
    __syncthreads();

    // sbf_h: 4 threads per row, 28 k's each, shfl-reduce
    {
        const int r = tid >> 2, q = tid & 3;
        float a8[NB];
#pragma unroll
        for (int o = 0; o < NB; o++) a8[o] = 0.f;
        const float* myrow = &stile[r * SP + q * 28];
        const float* myw = &ws_s[q * 28 * NB];
#pragma unroll 4
        for (int k = 0; k < 28; k++) {
            float s = myrow[k];
            float4 w0 = *(const float4*)&myw[k * NB];
            float4 w1 = *(const float4*)&myw[k * NB + 4];
            a8[0] = fmaf(s, w0.x, a8[0]); a8[1] = fmaf(s, w0.y, a8[1]);
            a8[2] = fmaf(s, w0.z, a8[2]); a8[3] = fmaf(s, w0.w, a8[3]);
            a8[4] = fmaf(s, w1.x, a8[4]); a8[5] = fmaf(s, w1.y, a8[5]);
            a8[6] = fmaf(s, w1.z, a8[6]); a8[7] = fmaf(s, w1.w, a8[7]);
        }
#pragma unroll
        for (int o = 0; o < NB; o++) {
            a8[o] += __shfl_xor_sync(0xffffffffu, a8[o], 1);
            a8[o] += __shfl_xor_sync(0xffffffffu, a8[o], 2);
        }
        if (q == 0) {
            *(float4*)&sbf_s[r * NB]     = make_float4(a8[0], a8[1], a8[2], a8[3]);
            *(float4*)&sbf_s[r * NB + 4] = make_float4(a8[4], a8[5], a8[6], a8[7]);
        }
    }
    __syncthreads();    // stile reads done before raw overwrites the region

    // gather x_kj rows into raw: 64*32 = 2048 float4
#pragma unroll
    for (int i = 0; i < 8; i++) {
        int idx = i * 256 + tid;
        int r = idx >> 5, c4 = idx & 31;
        int e = ek_s[r];
        *(float4*)&raw[r * BP + c4 * 4] = *(const float4*)&xkj[(size_t)e * H + c4 * 4];
    }
    __syncthreads();    // raw + sbf_s ready; NO MORE BARRIERS from here on

    // per-thread B base pointers (col fragment c0_j = ncol + j*8 + g)
    const float* bbase[4];
#pragma unroll
    for (int j = 0; j < 4; j++)
        bbase[j] = bw + (size_t)(ncol + j * 8 + g) * (NB * H) + t4;

    float acc[2][4][4];
    acc_zero(acc);

#pragma unroll
    for (int b = 0; b < NB; b++) {
        const float s0 = sbf_s[(r0)      * NB + b];
        const float s1 = sbf_s[(r0 + 8)  * NB + b];
        const float s2 = sbf_s[(r0 + 16) * NB + b];
        const float s3 = sbf_s[(r0 + 24) * NB + b];
        const int bo = b * H;

        // register double-buffered B fragments from L2
        uint32_t bc[4][2], bn[4][2];
#pragma unroll
        for (int j = 0; j < 4; j++) {
            bc[j][0] = __float_as_uint(__ldg(bbase[j] + bo));
            bc[j][1] = __float_as_uint(__ldg(bbase[j] + bo + 4));
        }
#pragma unroll
        for (int ks = 0; ks < 16; ks++) {
            const int k0 = ks * 8;
            if (ks < 15) {
#pragma unroll
                for (int j = 0; j < 4; j++) {
                    bn[j][0] = __float_as_uint(__ldg(bbase[j] + bo + k0 + 8));
                    bn[j][1] = __float_as_uint(__ldg(bbase[j] + bo + k0 + 12));
                }
            }
            uint32_t a[2][4];
            a[0][0] = cvu(raw[(r0)      * BP + k0 + t4] * s0);
            a[0][1] = cvu(raw[(r0 + 8)  * BP + k0 + t4] * s1);
            a[0][2] = cvu(raw[(r0)      * BP + k0 + t4 + 4] * s0);
            a[0][3] = cvu(raw[(r0 + 8)  * BP + k0 + t4 + 4] * s1);
            a[1][0] = cvu(raw[(r0 + 16) * BP + k0 + t4] * s2);
            a[1][1] = cvu(raw[(r0 + 24) * BP + k0 + t4] * s3);
            a[1][2] = cvu(raw[(r0 + 16) * BP + k0 + t4 + 4] * s2);
            a[1][3] = cvu(raw[(r0 + 24) * BP + k0 + t4 + 4] * s3);
#pragma unroll
            for (int i = 0; i < 2; i++)
#pragma unroll
                for (int j = 0; j < 4; j++)
                    mma_tf32(acc[i][j], a[i], bc[j]);
#pragma unroll
            for (int j = 0; j < 4; j++) {
                bc[j][0] = bn[j][0];
                bc[j][1] = bn[j][1];
            }
        }
    }

    // scatter-add epilogue
#pragma unroll
    for (int i = 0; i < 2; i++) {
#pragma unroll
        for (int half = 0; half < 2; half++) {
            int r = mrow + i * 16 + half * 8 + g;
            int t = tBase + r;
            if (t >= T) continue;
            float* dst = &hout[(size_t)ji_s[r] * H];
#pragma unroll
            for (int j = 0; j < 4; j++) {
                int col = ncol + j * 8 + t4 * 2;
                atomicAdd(dst + col,     acc[i][j][half * 2 + 0]);
                atomicAdd(dst + col + 1, acc[i][j][half * 2 + 1]);
            }
        }
    }
}

// ================= weight prep ===================================================
struct W9 { const float* p[9]; };
__global__ void transpose_w(W9 ws, float* __restrict__ out)
{
    int w = blockIdx.y;
    const float* in = ws.p[w];
    float* o = out + (size_t)w * H * H;
    int idx = blockIdx.x * 256 + threadIdx.x;
    int n = idx >> 7, k = idx & 127;
    o[n * H + k] = tf32r(in[k * H + n]);
}
__global__ void round_bilw(const float* __restrict__ in, float* __restrict__ out)
{
    int idx = blockIdx.x * 256 + threadIdx.x;
    if (idx < H * NB * H) out[idx] = tf32r(in[idx]);
}

// ================= launch ========================================================
extern "C" void kernel_launch(void* const* d_in, const int* in_sizes, int n_in,
                              void* d_out, int out_size)
{
    const float* x      = (const float*)d_in[0];
    const float* rbf    = (const float*)d_in[1];
    const float* sbf    = (const float*)d_in[2];
    const int*   kj     = (const int*)  d_in[3];
    const int*   ji     = (const int*)  d_in[4];
    const float* rbf_W  = (const float*)d_in[5];
    const float* sbf_W  = (const float*)d_in[6];
    const float* ji_W   = (const float*)d_in[7];
    const float* ji_b   = (const float*)d_in[8];
    const float* kj_W   = (const float*)d_in[9];
    const float* kj_b   = (const float*)d_in[10];
    const float* bil_W  = (const float*)d_in[11];
    const float* pre_b1 = (const float*)d_in[13];
    const float* pre_b2 = (const float*)d_in[15];
    const float* pre_b3 = (const float*)d_in[17];
    const float* post_b1 = (const float*)d_in[19];
    const float* post_b2 = (const float*)d_in[21];
    const float* post_b3 = (const float*)d_in[23];
    const float* post_b4 = (const float*)d_in[25];
    float* out = (float*)d_out;

    const int E = in_sizes[0] / H;
    const int T = in_sizes[3];

    float *p_h, *p_xkj, *p_wt, *p_bw;
    cudaGetSymbolAddress((void**)&p_h,    g_h);
    cudaGetSymbolAddress((void**)&p_xkj,  g_xkj);
    cudaGetSymbolAddress((void**)&p_wt,   g_wt);
    cudaGetSymbolAddress((void**)&p_bw,   g_bw);

    cudaFuncSetAttribute(fused_jikj, cudaFuncAttributeMaxDynamicSharedMemorySize, FJ_SMEM);
    cudaFuncSetAttribute(fused_pre,  cudaFuncAttributeMaxDynamicSharedMemorySize, FP_SMEM);
    cudaFuncSetAttribute(fused_post, cudaFuncAttributeMaxDynamicSharedMemorySize, FP_SMEM);
    cudaFuncSetAttribute(triplet_fused, cudaFuncAttributeMaxDynamicSharedMemorySize, TL_SMEM);

    const int gE = (E + 127) / 128;
    const int gT = (T + 63) / 64;

    // 0. weight prep
    W9 ws;
    ws.p[0] = ji_W; ws.p[1] = kj_W;
    ws.p[2] = (const float*)d_in[12]; ws.p[3] = (const float*)d_in[14]; ws.p[4] = (const float*)d_in[16];
    ws.p[5] = (const float*)d_in[18]; ws.p[6] = (const float*)d_in[20];
    ws.p[7] = (const float*)d_in[22]; ws.p[8] = (const float*)d_in[24];
    transpose_w<<<dim3(64, 9), 256>>>(ws, p_wt);
    round_bilw<<<(H * NB * H + 255) / 256, 256>>>(bil_W, p_bw);

    // 1. x_kj -> g_xkj, x_ji -> g_h (+ in-smem rbf_h)
    fused_jikj<<<gE, 512, FJ_SMEM>>>(x, rbf, rbf_W,
                                     p_wt + 1 * H * H, kj_b,
                                     p_wt + 0 * H * H, ji_b,
                                     p_xkj, p_h, E);
    // 2. triplet: sbf_h in-kernel + bilinear (B from L2) + scatter-add into g_h
    triplet_fused<<<gT, 256, TL_SMEM>>>(p_xkj, sbf, sbf_W, kj, ji, p_bw, p_h, T);
    // 3. pre-chain (3 GEMMs fused): g_h -> g_h (in-place per CTA slice)
    fused_pre<<<gE, 512, FP_SMEM>>>(p_h, x,
                                    p_wt + 2 * H * H, pre_b1,
                                    p_wt + 3 * H * H, pre_b2,
                                    p_wt + 4 * H * H, pre_b3,
                                    p_h, E);
    // 4. post-chain (4 GEMMs fused): g_h -> out
    fused_post<<<gE, 512, FP_SMEM>>>(p_h,
                                     p_wt + 5 * H * H, post_b1,
                                     p_wt + 6 * H * H, post_b2,
                                     p_wt + 7 * H * H, post_b3,
                                     p_wt + 8 * H * H, post_b4,
                                     out, E);
}

// round 12
// speedup vs baseline: 1.5783x; 1.5783x over previous
#include <cuda_runtime.h>
#include <cstdint>

// ---------------- problem constants ----------------
#define E_MAX 100000
#define T_MAX 200000
#define H 128
#define NR 16
#define NSR 112
#define NB 8

// ---------------- scratch ----------------
__device__ float g_h   [(size_t)E_MAX * H];
__device__ float g_xkj [(size_t)E_MAX * H];
__device__ float g_wt  [(size_t)9 * H * H];      // 9 transposed+rounded weights [n][k]
__device__ float g_bw  [(size_t)H * NB * H];     // tf32-rounded, k-permuted bil_W copy

// ---------------- helpers ----------------
__device__ __forceinline__ float tf32r(float x) {
    float y; asm("cvt.rna.tf32.f32 %0, %1;" : "=f"(y) : "f"(x)); return y;
}
__device__ __forceinline__ uint32_t cvu(float x) { return __float_as_uint(tf32r(x)); }
__device__ __forceinline__ float silu_f(float v) {
    return v * (1.0f / (1.0f + __expf(-v)));
}
__device__ __forceinline__ uint32_t smem_u32(const void* p) {
    uint32_t a;
    asm("{ .reg .u64 t; cvta.to.shared.u64 t, %1; cvt.u32.u64 %0, t; }" : "=r"(a) : "l"(p));
    return a;
}
__device__ __forceinline__ void mma_tf32(float* c, const uint32_t* a, const uint32_t* b) {
    asm volatile(
        "mma.sync.aligned.m16n8k8.row.col.f32.tf32.tf32.f32 "
        "{%0,%1,%2,%3}, {%4,%5,%6,%7}, {%8,%9}, {%0,%1,%2,%3};"
        : "+f"(c[0]), "+f"(c[1]), "+f"(c[2]), "+f"(c[3])
        : "r"(a[0]), "r"(a[1]), "r"(a[2]), "r"(a[3]), "r"(b[0]), "r"(b[1]));
}

#define BP 132      // chain-kernel pitch (132 % 32 == 4, conflict-free LDS.32 frags)
#define BP2 136     // triplet pitch (136 % 32 == 8, conflict-free LDS.64 frags)
#define TILE_B (128 * BP * 4)   // 67584 bytes

// permutation within an 8-wide k-group: k = 4h+q  ->  2q+h
__device__ __forceinline__ int kperm(int k) {
    return (k & ~7) + 2 * (k & 3) + ((k >> 2) & 1);
}

// ---------------- shared GEMM building blocks (512 thr, warps 4m x 4n) ----------
__device__ __forceinline__ void acc_zero(float acc[2][4][4]) {
#pragma unroll
    for (int i = 0; i < 2; i++)
#pragma unroll
        for (int j = 0; j < 4; j++)
#pragma unroll
            for (int e = 0; e < 4; e++) acc[i][j][e] = 0.f;
}

__device__ __forceinline__ void mma_128(const float* __restrict__ At,
                                        const float* __restrict__ Bs,
                                        float acc[2][4][4],
                                        int r0, int ncol, int g, int t4)
{
#pragma unroll
    for (int ks = 0; ks < 16; ks++) {
        const int k0 = ks * 8;
        uint32_t a[2][4], bb[4][2];
        a[0][0] = __float_as_uint(At[(r0)      * BP + k0 + t4]);
        a[0][1] = __float_as_uint(At[(r0 + 8)  * BP + k0 + t4]);
        a[0][2] = __float_as_uint(At[(r0)      * BP + k0 + t4 + 4]);
        a[0][3] = __float_as_uint(At[(r0 + 8)  * BP + k0 + t4 + 4]);
        a[1][0] = __float_as_uint(At[(r0 + 16) * BP + k0 + t4]);
        a[1][1] = __float_as_uint(At[(r0 + 24) * BP + k0 + t4]);
        a[1][2] = __float_as_uint(At[(r0 + 16) * BP + k0 + t4 + 4]);
        a[1][3] = __float_as_uint(At[(r0 + 24) * BP + k0 + t4 + 4]);
#pragma unroll
        for (int j = 0; j < 4; j++) {
            int c0 = ncol + j * 8 + g;
            bb[j][0] = __float_as_uint(Bs[c0 * BP + k0 + t4]);
            bb[j][1] = __float_as_uint(Bs[c0 * BP + k0 + t4 + 4]);
        }
#pragma unroll
        for (int i = 0; i < 2; i++)
#pragma unroll
            for (int j = 0; j < 4; j++)
                mma_tf32(acc[i][j], a[i], bb[j]);
    }
}

__device__ __forceinline__ void stage_w(float* Bs, const float* __restrict__ W, int tid) {
#pragma unroll
    for (int i = 0; i < 8; i++) {
        int idx = i * 512 + tid;
        int r = idx >> 5, c4 = idx & 31;
        *(float4*)&Bs[r * BP + c4 * 4] = *(const float4*)&W[(size_t)r * H + c4 * 4];
    }
}
__device__ __forceinline__ void stage_tile_r(float* Tt, const float* __restrict__ A,
                                             int rowBase, int M, int tid) {
#pragma unroll
    for (int i = 0; i < 8; i++) {
        int idx = i * 512 + tid;
        int r = idx >> 5, c4 = idx & 31;
        int grow = rowBase + r;
        float4 v = (grow < M) ? *(const float4*)&A[(size_t)grow * H + c4 * 4]
                              : make_float4(0.f, 0.f, 0.f, 0.f);
        v.x = tf32r(v.x); v.y = tf32r(v.y); v.z = tf32r(v.z); v.w = tf32r(v.w);
        *(float4*)&Tt[r * BP + c4 * 4] = v;
    }
}
__device__ __forceinline__ void epi_to_tile(float* Tt, const float acc[2][4][4],
                                            const float* biasS,
                                            int mrow, int ncol, int g, int t4)
{
#pragma unroll
    for (int i = 0; i < 2; i++)
#pragma unroll
        for (int half = 0; half < 2; half++) {
            int row = mrow + i * 16 + half * 8 + g;
#pragma unroll
            for (int j = 0; j < 4; j++) {
                int col = ncol + j * 8 + t4 * 2;
                float v0 = tf32r(silu_f(acc[i][j][half * 2 + 0] + biasS[col]));
                float v1 = tf32r(silu_f(acc[i][j][half * 2 + 1] + biasS[col + 1]));
                *(float2*)&Tt[row * BP + col] = make_float2(v0, v1);
            }
        }
}

// ================= fused x_ji / x_kj / rbf_h kernel ==============================
#define FJ_T0   0
#define FJ_BS   TILE_B
#define FJ_RB   (2 * TILE_B)
#define FJ_BIAS (3 * TILE_B)
#define FJ_SMEM (FJ_BIAS + 1024)
#define RP 20

__global__ void __launch_bounds__(512, 1)
fused_jikj(const float* __restrict__ x, const float* __restrict__ rbf,
           const float* __restrict__ rbfW,
           const float* __restrict__ kjWt, const float* __restrict__ kjb,
           const float* __restrict__ jiWt, const float* __restrict__ jib,
           float* __restrict__ xkj_out, float* __restrict__ h_out, int M)
{
    extern __shared__ char smem[];
    float* T0 = (float*)(smem + FJ_T0);
    float* Bs = (float*)(smem + FJ_BS);
    float* RB = (float*)(smem + FJ_RB);
    float* bKj = (float*)(smem + FJ_BIAS);
    float* bJi = (float*)(smem + FJ_BIAS + 512);
    float* rtile = Bs;
    float* rw    = Bs + 128 * RP;
    const int tid = threadIdx.x;
    const int wid = tid >> 5, lane = tid & 31;
    const int g = lane >> 2, t4 = lane & 3;
    const int rowBase = blockIdx.x * 128;
    const int mrow = (wid & 3) * 32;
    const int ncol = (wid >> 2) * 32;
    const int r0 = mrow + g;

    stage_tile_r(T0, x, rowBase, M, tid);
    {
        int r = tid >> 2, c4 = tid & 3;
        int grow = rowBase + r;
        float4 v = (grow < M) ? *(const float4*)&rbf[(size_t)grow * NR + c4 * 4]
                              : make_float4(0.f, 0.f, 0.f, 0.f);
        v.x = tf32r(v.x); v.y = tf32r(v.y); v.z = tf32r(v.z); v.w = tf32r(v.w);
        *(float4*)&rtile[r * RP + c4 * 4] = v;
    }
    {
        int n = tid >> 2, k0 = (tid & 3) * 4;
#pragma unroll
        for (int e = 0; e < 4; e++)
            rw[n * RP + k0 + e] = tf32r(rbfW[(size_t)(k0 + e) * H + n]);
    }
    if (tid < 32)       *(float4*)&bKj[tid * 4] = *(const float4*)&kjb[tid * 4];
    else if (tid < 64)  *(float4*)&bJi[(tid - 32) * 4] = *(const float4*)&jib[(tid - 32) * 4];
    __syncthreads();

    float acc[2][4][4];
    acc_zero(acc);
#pragma unroll
    for (int ks = 0; ks < 2; ks++) {
        const int k0 = ks * 8;
        uint32_t a[2][4], bb[4][2];
        a[0][0] = __float_as_uint(rtile[(r0)      * RP + k0 + t4]);
        a[0][1] = __float_as_uint(rtile[(r0 + 8)  * RP + k0 + t4]);
        a[0][2] = __float_as_uint(rtile[(r0)      * RP + k0 + t4 + 4]);
        a[0][3] = __float_as_uint(rtile[(r0 + 8)  * RP + k0 + t4 + 4]);
        a[1][0] = __float_as_uint(rtile[(r0 + 16) * RP + k0 + t4]);
        a[1][1] = __float_as_uint(rtile[(r0 + 24) * RP + k0 + t4]);
        a[1][2] = __float_as_uint(rtile[(r0 + 16) * RP + k0 + t4 + 4]);
        a[1][3] = __float_as_uint(rtile[(r0 + 24) * RP + k0 + t4 + 4]);
#pragma unroll
        for (int j = 0; j < 4; j++) {
            int c0 = ncol + j * 8 + g;
            bb[j][0] = __float_as_uint(rw[c0 * RP + k0 + t4]);
            bb[j][1] = __float_as_uint(rw[c0 * RP + k0 + t4 + 4]);
        }
#pragma unroll
        for (int i = 0; i < 2; i++)
#pragma unroll
            for (int j = 0; j < 4; j++)
                mma_tf32(acc[i][j], a[i], bb[j]);
    }
    __syncthreads();

#pragma unroll
    for (int i = 0; i < 2; i++)
#pragma unroll
        for (int half = 0; half < 2; half++) {
            int row = mrow + i * 16 + half * 8 + g;
#pragma unroll
            for (int j = 0; j < 4; j++) {
                int col = ncol + j * 8 + t4 * 2;
                *(float2*)&RB[row * BP + col] =
                    make_float2(acc[i][j][half * 2], acc[i][j][half * 2 + 1]);
            }
        }
    stage_w(Bs, kjWt, tid);
    __syncthreads();

    acc_zero(acc);
    mma_128(T0, Bs, acc, r0, ncol, g, t4);
#pragma unroll
    for (int i = 0; i < 2; i++)
#pragma unroll
        for (int half = 0; half < 2; half++) {
            int row = mrow + i * 16 + half * 8 + g;
            int grow = rowBase + row;
            if (grow >= M) continue;
#pragma unroll
            for (int j = 0; j < 4; j++) {
                int col = ncol + j * 8 + t4 * 2;
                float v0 = silu_f(silu_f(acc[i][j][half * 2 + 0] + bKj[col]));
                float v1 = silu_f(silu_f(acc[i][j][half * 2 + 1] + bKj[col + 1]));
                float2 m = *(float2*)&RB[row * BP + col];
                *(float2*)&xkj_out[(size_t)grow * H + col] = make_float2(v0 * m.x, v1 * m.y);
            }
        }
    __syncthreads();
    stage_w(Bs, jiWt, tid);
    __syncthreads();

    acc_zero(acc);
    mma_128(T0, Bs, acc, r0, ncol, g, t4);
#pragma unroll
    for (int i = 0; i < 2; i++)
#pragma unroll
        for (int half = 0; half < 2; half++) {
            int row = mrow + i * 16 + half * 8 + g;
            int grow = rowBase + row;
            if (grow >= M) continue;
#pragma unroll
            for (int j = 0; j < 4; j++) {
                int col = ncol + j * 8 + t4 * 2;
                float v0 = silu_f(silu_f(acc[i][j][half * 2 + 0] + bJi[col]));
                float v1 = silu_f(silu_f(acc[i][j][half * 2 + 1] + bJi[col + 1]));
                *(float2*)&h_out[(size_t)grow * H + col] = make_float2(v0, v1);
            }
        }
}

// ================= fused pre-chain: 3 GEMMs ======================================
#define FP_T0   0
#define FP_T1   TILE_B
#define FP_BS   (2 * TILE_B)
#define FP_BIAS (3 * TILE_B)
#define FP_SMEM (FP_BIAS + 2048)

__global__ void __launch_bounds__(512, 1)
fused_pre(const float* __restrict__ h, const float* __restrict__ x,
          const float* __restrict__ W1t, const float* __restrict__ b1,
          const float* __restrict__ W2t, const float* __restrict__ b2,
          const float* __restrict__ W3t, const float* __restrict__ b3,
          float* __restrict__ outg, int M)
{
    extern __shared__ char smem[];
    float* T0 = (float*)(smem + FP_T0);
    float* T1 = (float*)(smem + FP_T1);
    float* Bs = (float*)(smem + FP_BS);
    float* bS1 = (float*)(smem + FP_BIAS);
    float* bS2 = bS1 + 128;
    float* bS3 = bS2 + 128;
    const int tid = threadIdx.x;
    const int wid = tid >> 5, lane = tid & 31;
    const int g = lane >> 2, t4 = lane & 3;
    const int rowBase = blockIdx.x * 128;
    const int mrow = (wid & 3) * 32;
    const int ncol = (wid >> 2) * 32;
    const int r0 = mrow + g;

    stage_tile_r(T0, h, rowBase, M, tid);
    if (tid < 32)       *(float4*)&bS1[tid * 4] = *(const float4*)&b1[tid * 4];
    else if (tid < 64)  *(float4*)&bS2[(tid - 32) * 4] = *(const float4*)&b2[(tid - 32) * 4];
    else if (tid < 96)  *(float4*)&bS3[(tid - 64) * 4] = *(const float4*)&b3[(tid - 64) * 4];
    stage_w(Bs, W1t, tid);
    __syncthreads();

    float acc[2][4][4];
    acc_zero(acc);
    mma_128(T0, Bs, acc, r0, ncol, g, t4);
    __syncthreads();
    epi_to_tile(T1, acc, bS1, mrow, ncol, g, t4);
    stage_w(Bs, W2t, tid);
    __syncthreads();

    acc_zero(acc);
    mma_128(T1, Bs, acc, r0, ncol, g, t4);
    __syncthreads();
#pragma unroll
    for (int i = 0; i < 2; i++)
#pragma unroll
        for (int half = 0; half < 2; half++) {
            int row = mrow + i * 16 + half * 8 + g;
#pragma unroll
            for (int j = 0; j < 4; j++) {
                int col = ncol + j * 8 + t4 * 2;
                float2 res = *(float2*)&T0[row * BP + col];
                float v0 = tf32r(res.x + silu_f(acc[i][j][half * 2 + 0] + bS2[col]));
                float v1 = tf32r(res.y + silu_f(acc[i][j][half * 2 + 1] + bS2[col + 1]));
                *(float2*)&T1[row * BP + col] = make_float2(v0, v1);
            }
        }
    stage_w(Bs, W3t, tid);
    __syncthreads();

    acc_zero(acc);
    mma_128(T1, Bs, acc, r0, ncol, g, t4);
#pragma unroll
    for (int i = 0; i < 2; i++)
#pragma unroll
        for (int half = 0; half < 2; half++) {
            int row = mrow + i * 16 + half * 8 + g;
            int grow = rowBase + row;
            if (grow >= M) continue;
#pragma unroll
            for (int j = 0; j < 4; j++) {
                int col = ncol + j * 8 + t4 * 2;
                float2 xr = *(const float2*)&x[(size_t)grow * H + col];
                float v0 = silu_f(acc[i][j][half * 2 + 0] + bS3[col]) + xr.x;
                float v1 = silu_f(acc[i][j][half * 2 + 1] + bS3[col + 1]) + xr.y;
                *(float2*)&outg[(size_t)grow * H + col] = make_float2(v0, v1);
            }
        }
}

// ================= fused post-chain: 4 GEMMs =====================================
__global__ void __launch_bounds__(512, 1)
fused_post(const float* __restrict__ h,
           const float* __restrict__ W1t, const float* __restrict__ b1,
           const float* __restrict__ W2t, const float* __restrict__ b2,
           const float* __restrict__ W3t, const float* __restrict__ b3,
           const float* __restrict__ W4t, const float* __restrict__ b4,
           float* __restrict__ outg, int M)
{
    extern __shared__ char smem[];
    float* T0 = (float*)(smem + FP_T0);
    float* T1 = (float*)(smem + FP_T1);
    float* Bs = (float*)(smem + FP_BS);
    float* bS1 = (float*)(smem + FP_BIAS);
    float* bS2 = bS1 + 128;
    float* bS3 = bS2 + 128;
    float* bS4 = bS3 + 128;
    const int tid = threadIdx.x;
    const int wid = tid >> 5, lane = tid & 31;
    const int g = lane >> 2, t4 = lane & 3;
    const int rowBase = blockIdx.x * 128;
    const int mrow = (wid & 3) * 32;
    const int ncol = (wid >> 2) * 32;
    const int r0 = mrow + g;

    stage_tile_r(T0, h, rowBase, M, tid);
    if (tid < 32)       *(float4*)&bS1[tid * 4] = *(const float4*)&b1[tid * 4];
    else if (tid < 64)  *(float4*)&bS2[(tid - 32) * 4] = *(const float4*)&b2[(tid - 32) * 4];
    else if (tid < 96)  *(float4*)&bS3[(tid - 64) * 4] = *(const float4*)&b3[(tid - 64) * 4];
    else if (tid < 128) *(float4*)&bS4[(tid - 96) * 4] = *(const float4*)&b4[(tid - 96) * 4];
    stage_w(Bs, W1t, tid);
    __syncthreads();

    float acc[2][4][4];
    acc_zero(acc);
    mma_128(T0, Bs, acc, r0, ncol, g, t4);
    __syncthreads();
    epi_to_tile(T1, acc, bS1, mrow, ncol, g, t4);
    stage_w(Bs, W2t, tid);
    __syncthreads();

    acc_zero(acc);
    mma_128(T1, Bs, acc, r0, ncol, g, t4);
    __syncthreads();
#pragma unroll
    for (int i = 0; i < 2; i++)
#pragma unroll
        for (int half = 0; half < 2; half++) {
            int row = mrow + i * 16 + half * 8 + g;
#pragma unroll
            for (int j = 0; j < 4; j++) {
                int col = ncol + j * 8 + t4 * 2;
                float2 res = *(float2*)&T0[row * BP + col];
                float v0 = tf32r(res.x + silu_f(acc[i][j][half * 2 + 0] + bS2[col]));
                float v1 = tf32r(res.y + silu_f(acc[i][j][half * 2 + 1] + bS2[col + 1]));
                *(float2*)&T0[row * BP + col] = make_float2(v0, v1);
            }
        }
    stage_w(Bs, W3t, tid);
    __syncthreads();

    acc_zero(acc);
    mma_128(T0, Bs, acc, r0, ncol, g, t4);
    __syncthreads();
    epi_to_tile(T1, acc, bS3, mrow, ncol, g, t4);
    stage_w(Bs, W4t, tid);
    __syncthreads();

    acc_zero(acc);
    mma_128(T1, Bs, acc, r0, ncol, g, t4);
#pragma unroll
    for (int i = 0; i < 2; i++)
#pragma unroll
        for (int half = 0; half < 2; half++) {
            int row = mrow + i * 16 + half * 8 + g;
            int grow = rowBase + row;
            if (grow >= M) continue;
#pragma unroll
            for (int j = 0; j < 4; j++) {
                int col = ncol + j * 8 + t4 * 2;
                float2 res = *(float2*)&T0[row * BP + col];
                float v0 = res.x + silu_f(acc[i][j][half * 2 + 0] + bS4[col]);
                float v1 = res.y + silu_f(acc[i][j][half * 2 + 1] + bS4[col + 1]);
                *(float2*)&outg[(size_t)grow * H + col] = make_float2(v0, v1);
            }
        }
}

// ================= fused triplet: R9 geometry + k-permuted LDS.64 layout =========
// 64 triplets x 128 cols, 256 threads, 8 warps (2m x 4n), warp tile 32x32.
#define TR2J   0                        // ji   [64] int
#define TR2K   256                      // ekj  [64] int
#define TR2S   512                      // sbf_s [64][8]     2 KB
#define TR2W   2560                     // ws_s  [112][8]    3.5 KB
#define TR2RAW 6144                     // raw  [64][BP2]    34816 B
#define TR2B   (TR2RAW + 64 * BP2 * 4)  // Bs   [128][BP2]   69632 B
#define TR2_SMEM (TR2B + 128 * BP2 * 4) // 110592 B -> 2 CTAs/SM
#define SP 113                          // sbf staging pitch

// stage one (k-permuted) bilW channel into Bs via cp.async (256 threads)
__device__ __forceinline__ void cpasync_bw2(uint32_t bs_u32, const float* __restrict__ bw,
                                            int b, int tid)
{
#pragma unroll
    for (int i = 0; i < 16; i++) {
        int c = i * 256 + tid;          // 0..4095 chunks of 16B
        int r = c >> 5, c4 = c & 31;
        uint32_t dst = bs_u32 + (uint32_t)(r * BP2 + c4 * 4) * 4u;
        const float* src = bw + (size_t)r * (NB * H) + b * H + c4 * 4;
        asm volatile("cp.async.cg.shared.global [%0], [%1], 16;" :: "r"(dst), "l"(src));
    }
    asm volatile("cp.async.commit_group;" ::: "memory");
}

__global__ void __launch_bounds__(256, 2)
triplet_fused(const float* __restrict__ xkj,
              const float* __restrict__ sbf, const float* __restrict__ sbfW,
              const int* __restrict__ kj, const int* __restrict__ ji,
              const float* __restrict__ bw, float* __restrict__ hout, int T)
{
    extern __shared__ char smem[];
    int* ji_s = (int*)(smem + TR2J);
    int* ek_s = (int*)(smem + TR2K);
    float* sbf_s = (float*)(smem + TR2S);
    float* ws_s = (float*)(smem + TR2W);
    float* raw = (float*)(smem + TR2RAW);
    float* Bs = (float*)(smem + TR2B);
    float* stile = Bs;                  // [64][SP] sbf staging (28.9KB, reused)
    const int tid = threadIdx.x;
    const int wid = tid >> 5, lane = tid & 31;
    const int g = lane >> 2, t4 = lane & 3;
    const int tBase = blockIdx.x * 64;
    const int mrow = (wid & 1) * 32;
    const int ncol = (wid >> 1) * 32;
    const int r0 = mrow + g;
    const uint32_t bs_u32 = smem_u32(Bs);

    if (tid < 64) {
        int t = tBase + tid;
        ji_s[tid] = (t < T) ? ji[t] : 0;
        ek_s[tid] = (t < T) ? kj[t] : 0;
    }
    if (tid < 224) *(float4*)&ws_s[tid * 4] = *(const float4*)&sbfW[tid * 4];
#pragma unroll
    for (int i = 0; i < 7; i++) {
        int idx = i * 256 + tid;
        int r = idx / 28, c = idx % 28;
        int t = tBase + r;
        float4 v = (t < T) ? *(const float4*)&sbf[(size_t)t * NSR + c * 4]
                           : make_float4(0.f, 0.f, 0.f, 0.f);
        stile[r * SP + c * 4 + 0] = v.x;
        stile[r * SP + c * 4 + 1] = v.y;
        stile[r * SP + c * 4 + 2] = v.z;
        stile[r * SP + c * 4 + 3] = v.w;
    }
    __syncthreads();

    // sbf_h: 4 threads per row, 28 k's each, shfl-reduce
    {
        const int r = tid >> 2, q = tid & 3;
        float a8[NB];
#pragma unroll
        for (int o = 0; o < NB; o++) a8[o] = 0.f;
        const float* myrow = &stile[r * SP + q * 28];
        const float* myw = &ws_s[q * 28 * NB];
#pragma unroll 4
        for (int k = 0; k < 28; k++) {
            float s = myrow[k];
            float4 w0 = *(const float4*)&myw[k * NB];
            float4 w1 = *(const float4*)&myw[k * NB + 4];
            a8[0] = fmaf(s, w0.x, a8[0]); a8[1] = fmaf(s, w0.y, a8[1]);
            a8[2] = fmaf(s, w0.z, a8[2]); a8[3] = fmaf(s, w0.w, a8[3]);
            a8[4] = fmaf(s, w1.x, a8[4]); a8[5] = fmaf(s, w1.y, a8[5]);
            a8[6] = fmaf(s, w1.z, a8[6]); a8[7] = fmaf(s, w1.w, a8[7]);
        }
#pragma unroll
        for (int o = 0; o < NB; o++) {
            a8[o] += __shfl_xor_sync(0xffffffffu, a8[o], 1);
            a8[o] += __shfl_xor_sync(0xffffffffu, a8[o], 2);
        }
        if (q == 0) {
            *(float4*)&sbf_s[r * NB]     = make_float4(a8[0], a8[1], a8[2], a8[3]);
            *(float4*)&sbf_s[r * NB + 4] = make_float4(a8[4], a8[5], a8[6], a8[7]);
        }
    }
    // gather x_kj rows into raw, k-permuted: 64 rows x 16 groups, 4 tasks/thread
#pragma unroll
    for (int i = 0; i < 4; i++) {
        int idx = i * 256 + tid;        // 0..1023
        int r = idx >> 4, grp = idx & 15;
        int e = ek_s[r];
        const float* src = &xkj[(size_t)e * H + grp * 8];
        float4 lo = *(const float4*)src;
        float4 hi = *(const float4*)(src + 4);
        float2* dst = (float2*)&raw[r * BP2 + grp * 8];
        dst[0] = make_float2(lo.x, hi.x);
        dst[1] = make_float2(lo.y, hi.y);
        dst[2] = make_float2(lo.z, hi.z);
        dst[3] = make_float2(lo.w, hi.w);
    }

    float acc[2][4][4];
    acc_zero(acc);

    for (int b = 0; b < NB; b++) {
        __syncthreads();                // prev mma Bs reads done (1st iter: stile reads done)
        cpasync_bw2(bs_u32, bw, b, tid);
        asm volatile("cp.async.wait_group 0;" ::: "memory");
        __syncthreads();

        const float s0 = sbf_s[(r0)      * NB + b];
        const float s1 = sbf_s[(r0 + 8)  * NB + b];
        const float s2 = sbf_s[(r0 + 16) * NB + b];
        const float s3 = sbf_s[(r0 + 24) * NB + b];

#pragma unroll
        for (int ks = 0; ks < 16; ks++) {
            const int k0 = ks * 8;
            uint32_t a[2][4], bb[4][2];
            float2 v00 = *(float2*)&raw[(r0)      * BP2 + k0 + 2 * t4];
            float2 v01 = *(float2*)&raw[(r0 + 8)  * BP2 + k0 + 2 * t4];
            float2 v10 = *(float2*)&raw[(r0 + 16) * BP2 + k0 + 2 * t4];
            float2 v11 = *(float2*)&raw[(r0 + 24) * BP2 + k0 + 2 * t4];
            a[0][0] = cvu(v00.x * s0); a[0][2] = cvu(v00.y * s0);
            a[0][1] = cvu(v01.x * s1); a[0][3] = cvu(v01.y * s1);
            a[1][0] = cvu(v10.x * s2); a[1][2] = cvu(v10.y * s2);
            a[1][1] = cvu(v11.x * s3); a[1][3] = cvu(v11.y * s3);
#pragma unroll
            for (int j = 0; j < 4; j++) {
                int c0 = ncol + j * 8 + g;
                float2 w = *(float2*)&Bs[c0 * BP2 + k0 + 2 * t4];
                bb[j][0] = __float_as_uint(w.x);
                bb[j][1] = __float_as_uint(w.y);
            }
#pragma unroll
            for (int i = 0; i < 2; i++)
#pragma unroll
                for (int j = 0; j < 4; j++)
                    mma_tf32(acc[i][j], a[i], bb[j]);
        }
    }

    // scatter-add epilogue
#pragma unroll
    for (int i = 0; i < 2; i++) {
#pragma unroll
        for (int half = 0; half < 2; half++) {
            int r = mrow + i * 16 + half * 8 + g;
            int t = tBase + r;
            if (t >= T) continue;
            float* dst = &hout[(size_t)ji_s[r] * H];
#pragma unroll
            for (int j = 0; j < 4; j++) {
                int col = ncol + j * 8 + t4 * 2;
                atomicAdd(dst + col,     acc[i][j][half * 2 + 0]);
                atomicAdd(dst + col + 1, acc[i][j][half * 2 + 1]);
            }
        }
    }
}

// ================= weight prep ===================================================
struct W9 { const float* p[9]; };
__global__ void transpose_w(W9 ws, float* __restrict__ out)
{
    int w = blockIdx.y;
    const float* in = ws.p[w];
    float* o = out + (size_t)w * H * H;
    int idx = blockIdx.x * 256 + threadIdx.x;
    int n = idx >> 7, k = idx & 127;
    o[n * H + k] = tf32r(in[k * H + n]);
}
// round + k-permute bil_W: out[row][perm(k)] = tf32r(in[row][k])
__global__ void round_bilw(const float* __restrict__ in, float* __restrict__ out)
{
    int idx = blockIdx.x * 256 + threadIdx.x;
    if (idx >= H * NB * H) return;
    int k = idx & 127;
    int base = idx - k;
    int p = (k & ~7) + 2 * (k & 3) + ((k >> 2) & 1);
    out[base + p] = tf32r(in[idx]);
}

// ================= launch ========================================================
extern "C" void kernel_launch(void* const* d_in, const int* in_sizes, int n_in,
                              void* d_out, int out_size)
{
    const float* x      = (const float*)d_in[0];
    const float* rbf    = (const float*)d_in[1];
    const float* sbf    = (const float*)d_in[2];
    const int*   kj     = (const int*)  d_in[3];
    const int*   ji     = (const int*)  d_in[4];
    const float* rbf_W  = (const float*)d_in[5];
    const float* sbf_W  = (const float*)d_in[6];
    const float* ji_W   = (const float*)d_in[7];
    const float* ji_b   = (const float*)d_in[8];
    const float* kj_W   = (const float*)d_in[9];
    const float* kj_b   = (const float*)d_in[10];
    const float* bil_W  = (const float*)d_in[11];
    const float* pre_b1 = (const float*)d_in[13];
    const float* pre_b2 = (const float*)d_in[15];
    const float* pre_b3 = (const float*)d_in[17];
    const float* post_b1 = (const float*)d_in[19];
    const float* post_b2 = (const float*)d_in[21];
    const float* post_b3 = (const float*)d_in[23];
    const float* post_b4 = (const float*)d_in[25];
    float* out = (float*)d_out;

    const int E = in_sizes[0] / H;
    const int T = in_sizes[3];

    float *p_h, *p_xkj, *p_wt, *p_bw;
    cudaGetSymbolAddress((void**)&p_h,    g_h);
    cudaGetSymbolAddress((void**)&p_xkj,  g_xkj);
    cudaGetSymbolAddress((void**)&p_wt,   g_wt);
    cudaGetSymbolAddress((void**)&p_bw,   g_bw);

    cudaFuncSetAttribute(fused_jikj, cudaFuncAttributeMaxDynamicSharedMemorySize, FJ_SMEM);
    cudaFuncSetAttribute(fused_pre,  cudaFuncAttributeMaxDynamicSharedMemorySize, FP_SMEM);
    cudaFuncSetAttribute(fused_post, cudaFuncAttributeMaxDynamicSharedMemorySize, FP_SMEM);
    cudaFuncSetAttribute(triplet_fused, cudaFuncAttributeMaxDynamicSharedMemorySize, TR2_SMEM);

    const int gE = (E + 127) / 128;
    const int gT = (T + 63) / 64;

    // 0. weight prep
    W9 ws;
    ws.p[0] = ji_W; ws.p[1] = kj_W;
    ws.p[2] = (const float*)d_in[12]; ws.p[3] = (const float*)d_in[14]; ws.p[4] = (const float*)d_in[16];
    ws.p[5] = (const float*)d_in[18]; ws.p[6] = (const float*)d_in[20];
    ws.p[7] = (const float*)d_in[22]; ws.p[8] = (const float*)d_in[24];
    transpose_w<<<dim3(64, 9), 256>>>(ws, p_wt);
    round_bilw<<<(H * NB * H + 255) / 256, 256>>>(bil_W, p_bw);

    // 1. x_kj -> g_xkj, x_ji -> g_h (+ in-smem rbf_h)
    fused_jikj<<<gE, 512, FJ_SMEM>>>(x, rbf, rbf_W,
                                     p_wt + 1 * H * H, kj_b,
                                     p_wt + 0 * H * H, ji_b,
                                     p_xkj, p_h, E);
    // 2. triplet: sbf_h in-kernel + bilinear + scatter-add into g_h
    triplet_fused<<<gT, 256, TR2_SMEM>>>(p_xkj, sbf, sbf_W, kj, ji, p_bw, p_h, T);
    // 3. pre-chain (3 GEMMs fused): g_h -> g_h (in-place per CTA slice)
    fused_pre<<<gE, 512, FP_SMEM>>>(p_h, x,
                                    p_wt + 2 * H * H, pre_b1,
                                    p_wt + 3 * H * H, pre_b2,
                                    p_wt + 4 * H * H, pre_b3,
                                    p_h, E);
    // 4. post-chain (4 GEMMs fused): g_h -> out
    fused_post<<<gE, 512, FP_SMEM>>>(p_h,
                                     p_wt + 5 * H * H, post_b1,
                                     p_wt + 6 * H * H, post_b2,
                                     p_wt + 7 * H * H, post_b3,
                                     p_wt + 8 * H * H, post_b4,
                                     out, E);
}